// round 16
// baseline (speedup 1.0000x reference)
#include <cuda_runtime.h>
#include <cuda_bf16.h>

#define NL    64
#define HH    50
#define G4    200
#define DIN   60
#define BATCH 32
#define TT    2048
#define DOUT  50
#define BS    16
#define NSL   2
#define RINGN 16
#define TPB   480   // warps 0-12: H/MMA group (tid 0..415), warps 13-14: X group (tid 416..479)

#define KST   22    // folded K: 10 h-ksteps + 12 x-ksteps
#define KH    10
// ---- scratch (device globals) ----
__device__ float d_ring[(NL - 1) * RINGN * NSL * HH * BS];  // [l][slot][s][u][16]
__device__ int   d_prog[NSL * NL];
__device__ int   d_cons[NSL * NL];
__device__ float d_xT[TT * NSL * DIN * BS];                 // [t][s][d][16]
__device__ float d_hT[TT * NSL * HH * BS];                  // [t][s][u][16]

// lstm smem (float indices)
#define OFF_BIAS 0       // [208]
#define OFF_G    208     // [208][20]
#define OFF_ZH   4368    // h-region zpack: 80 kpairs x 24 words = 1920
#define OFF_ZX   6288    // x-region zpack: 2 x (96 kpairs x 24 words = 2304)
#define SMEM_FLOATS 10896
// fc smem
#define FOFF_W  0
#define FOFF_B  2512
#define FOFF_H  2576

__device__ __forceinline__ float sigf(float x) {
    return __fdividef(1.0f, 1.0f + __expf(-x));
}
__device__ __forceinline__ float tanhfast(float x) {
    return 1.0f - __fdividef(2.0f, __expf(2.0f * x) + 1.0f);
}
__device__ __forceinline__ int ld_acquire_gpu(const int* p) {
    int v;
    asm volatile("ld.acquire.gpu.global.b32 %0, [%1];" : "=r"(v) : "l"(p) : "memory");
    return v;
}
__device__ __forceinline__ void st_release_gpu(int* p, int v) {
    asm volatile("st.release.gpu.global.b32 [%0], %1;" :: "l"(p), "r"(v) : "memory");
}
__device__ __forceinline__ void mma_bf16(float* d, const unsigned int* a,
                                         unsigned int b0, unsigned int b1) {
    asm volatile(
        "mma.sync.aligned.m16n8k16.row.col.f32.bf16.bf16.f32 "
        "{%0,%1,%2,%3}, {%4,%5,%6,%7}, {%8,%9}, {%0,%1,%2,%3};"
        : "+f"(d[0]), "+f"(d[1]), "+f"(d[2]), "+f"(d[3])
        : "r"(a[0]), "r"(a[1]), "r"(a[2]), "r"(a[3]), "r"(b0), "r"(b1));
}

#define BAR_SYNC(id, n)   asm volatile("bar.sync %0, %1;"   :: "r"(id), "r"(n) : "memory")
#define BAR_ARRIVE(id, n) asm volatile("bar.arrive %0, %1;" :: "r"(id), "r"(n) : "memory")

// pair-packed zpack write: word row stride 24, u16 idx = ((pos>>1)*24 + n)*2 + (pos&1)
__device__ __forceinline__ void zput(__nv_bfloat16* z, int n, int pos, __nv_bfloat16 v) {
    z[((pos >> 1) * 24 + n) * 2 + (pos & 1)] = v;
}
// h-region: pos {kk, 50+kk, 100+kk} <- {z1, z2, z1}
__device__ __forceinline__ void stage_zh(__nv_bfloat16* zh, int n, int kk, float v) {
    __nv_bfloat16 z1 = __float2bfloat16(v);
    __nv_bfloat16 z2 = __float2bfloat16(v - __bfloat162float(z1));
    zput(zh, n, kk, z1);
    zput(zh, n, 50 + kk, z2);
    zput(zh, n, 100 + kk, z1);
}
// x-region: pos {d, 60+d, 120+d} <- {z1, z2, z1}
__device__ __forceinline__ void stage_zx(__nv_bfloat16* zx, int n, int d, float v) {
    __nv_bfloat16 z1 = __float2bfloat16(v);
    __nv_bfloat16 z2 = __float2bfloat16(v - __bfloat162float(z1));
    zput(zx, n, d, z1);
    zput(zx, n, 60 + d, z2);
    zput(zx, n, 120 + d, z1);
}

// folded-K weight bits for global column col (0..351), gate row j
__device__ __forceinline__ unsigned short wbits(const float* wh, const float* wx,
                                                int j, int col, int K1x) {
    float w;
    int seg;
    if (col < 160) {
        if (col >= 150) return 0;
        seg = col / 50;
        w = wh[j * HH + (col % 50)];
    } else {
        int xc = col - 160;
        if (xc >= 180) return 0;
        seg = xc / 60;
        int kz = xc % 60;
        if (kz >= K1x) return 0;
        w = wx[j * K1x + kz];
    }
    __nv_bfloat16 w1 = __float2bfloat16(w);
    __nv_bfloat16 res = (seg == 2) ? __float2bfloat16(w - __bfloat162float(w1)) : w1;
    return *reinterpret_cast<unsigned short*>(&res);
}

__global__ void xpose_kernel(const float* __restrict__ x) {
    if (blockIdx.x == 0 && threadIdx.x < NSL * NL) {
        d_prog[threadIdx.x] = 0;
        d_cons[threadIdx.x] = 0;
    }
    int idx = blockIdx.x * blockDim.x + threadIdx.x;  // (b*DIN+d)*T + t
    if (idx >= BATCH * DIN * TT) return;
    int t = idx % TT;
    int bd = idx / TT;
    int d = bd % DIN, b = bd / DIN;
    d_xT[(((size_t)t * NSL + b / BS) * DIN + d) * BS + (b % BS)] = x[idx];
}

__global__ void __launch_bounds__(TPB, 1) lstm_kernel(
    const float* __restrict__ hn,  const float* __restrict__ cn,
    const float* __restrict__ Wih0, const float* __restrict__ Wih,
    const float* __restrict__ Whh, const float* __restrict__ bih,
    const float* __restrict__ bhh, const float* __restrict__ fcw,
    const float* __restrict__ fcb, float* __restrict__ out, int has_state)
{
    extern __shared__ float sm[];
    const int tid  = threadIdx.x;
    const int lane = tid & 31;
    const int w    = tid >> 5;

    // ================= FC consumer role (blocks 128,129) =================
    if (blockIdx.x >= NL * NSL) {
        const int s = blockIdx.x - NL * NSL;
        float* sm_w  = sm + FOFF_W;
        float* sm_fb = sm + FOFF_B;
        float* sm_h  = sm + FOFF_H;
        for (int i = tid; i < DOUT * HH; i += TPB) sm_w[i] = fcw[i];
        for (int i = tid; i < DOUT; i += TPB)      sm_fb[i] = fcb[i];
        __syncthreads();
        const int* prog63 = &d_prog[s * NL + NL - 1];
        for (int t = 0; t < TT; ++t) {
            if (lane == 0) { while (ld_acquire_gpu(prog63) < t + 1) __nanosleep(128); }
            __syncwarp();
            const float* hp = d_hT + ((size_t)t * NSL + s) * HH * BS;
            for (int idx = tid; idx < HH * 4; idx += TPB) {
                float4 v = __ldcg((const float4*)(hp + idx * 4));
                *(float4*)(sm_h + idx * 4) = v;
            }
            __syncthreads();
            if (tid < G4) {
                const int o  = tid % DOUT;
                const int bq = tid / DOUT;
#pragma unroll
                for (int i = 0; i < 4; ++i) {
                    int b = bq * 4 + i;
                    float acc = sm_fb[o];
#pragma unroll 5
                    for (int u = 0; u < HH; ++u)
                        acc = fmaf(sm_h[u * BS + b], sm_w[o * HH + u], acc);
                    out[((size_t)(s * BS + b) * DOUT + o) * TT + t] = sigf(acc);
                }
            }
            __syncthreads();
        }
        return;
    }

    // ========================= LSTM layer role =========================
    const int layer = blockIdx.x >> 1;
    const int s     = blockIdx.x & 1;
    const int b0    = s * BS;
    const int K1x   = (layer == 0) ? DIN : HH;

    float* sm_b = sm + OFF_BIAS;
    float* sm_g = sm + OFF_G;
    __nv_bfloat16* zh = reinterpret_cast<__nv_bfloat16*>(sm + OFF_ZH);

    // ---- init: zero zpacks (NaN safety for pad slots), bias, h0 ----
    for (int i = tid; i < SMEM_FLOATS - OFF_ZH; i += TPB) sm[OFF_ZH + i] = 0.0f;
    for (int jj = tid; jj < G4; jj += TPB)
        sm_b[jj] = bih[layer * G4 + jj] + bhh[layer * G4 + jj];
    __syncthreads();   // zpack zeroed before staging h0
    if (tid < G4) {
        int u = tid % HH, bq = tid / HH;
#pragma unroll
        for (int i = 0; i < 4; ++i) {
            int b = 4 * bq + i;
            stage_zh(zh, b, u, hn[((size_t)layer * BATCH + b0 + b) * HH + u]);
        }
    }
    __syncthreads();

    int* prog_prev = (layer > 0)      ? &d_prog[s * NL + layer - 1] : 0;
    int* cons_next = (layer < NL - 1) ? &d_cons[s * NL + layer + 1] : 0;
    int* prog_me   = &d_prog[s * NL + layer];
    int* cons_me   = &d_cons[s * NL + layer];

    if (w < 13) {
        // ======================= H-group (MMA + C) =======================
        // A fragments into registers (once per layer)
        unsigned int afr[KST][4];
        {
            const float* wh = Whh + (size_t)layer * G4 * HH;
            const float* wx = (layer == 0) ? Wih0 : (Wih + (size_t)(layer - 1) * G4 * HH);
            const int gr = lane >> 2, cp = (lane & 3) * 2;
            for (int kk = 0; kk < KST; ++kk) {
#pragma unroll
                for (int r = 0; r < 4; ++r) {
                    int j = w * 16 + gr + (r & 1) * 8;
                    int c = kk * 16 + cp + (r >> 1) * 8;
                    unsigned int pr = 0;
                    if (j < G4) {
                        pr  = (unsigned int)wbits(wh, wx, j, c, K1x);
                        pr |= ((unsigned int)wbits(wh, wx, j, c + 1, K1x)) << 16;
                    }
                    afr[kk][r] = pr;
                }
            }
        }
        // cell state: threads 0..399, u = tid%50, bq8 = tid/50 (0..7), 2 batches each
        float creg[2];
        const int u_c  = tid % HH;
        const int bq8  = (tid < 400) ? (tid / HH) : 0;
        if (tid < 400) {
#pragma unroll
            for (int i = 0; i < 2; ++i)
                creg[i] = cn[((size_t)layer * BATCH + b0 + 2 * bq8 + i) * HH + u_c];
        }

        const int zb = (lane & 3) * 24 + (lane >> 2);
        const float* zhw = sm + OFF_ZH;
        const int gr = lane >> 2, cp = (lane & 3) * 2;
        const int j0 = w * 16 + gr;
        int cons_cache = 0;   // lane0-only cached view of cons_next

        for (int t = 0; t < TT; ++t) {
            BAR_SYNC(2 + (t & 1), TPB);        // x(t) staged by X-group

            // ---- backpressure (cached, hoisted: latency overlaps MMA) ----
            if (layer < NL - 1 && t >= RINGN && lane == 0) {
                int need = t - RINGN + 1;
                if (cons_cache < need) {
                    cons_cache = ld_acquire_gpu(cons_next);
                    while (cons_cache < need) {
                        __nanosleep(32);
                        cons_cache = ld_acquire_gpu(cons_next);
                    }
                }
            }

            // ---- MMA: gates[208,16] = A . Z  (k-split accumulators) ----
            {
                float a0e[4] = {0.f, 0.f, 0.f, 0.f};
                float a1e[4] = {0.f, 0.f, 0.f, 0.f};
                float a0o[4] = {0.f, 0.f, 0.f, 0.f};
                float a1o[4] = {0.f, 0.f, 0.f, 0.f};
                const float* zxw = sm + OFF_ZX + (t & 1) * 2304;
#pragma unroll
                for (int kk = 0; kk < KST; kk += 2) {
                    const float* zpA = (kk < KH) ? (zhw + kk * 192 + zb)
                                                 : (zxw + (kk - KH) * 192 + zb);
                    const float* zpB = ((kk + 1) < KH) ? (zhw + (kk + 1) * 192 + zb)
                                                       : (zxw + (kk + 1 - KH) * 192 + zb);
                    unsigned int eb00 = __float_as_uint(zpA[0]);
                    unsigned int eb01 = __float_as_uint(zpA[96]);
                    unsigned int eb10 = __float_as_uint(zpA[8]);
                    unsigned int eb11 = __float_as_uint(zpA[104]);
                    unsigned int ob00 = __float_as_uint(zpB[0]);
                    unsigned int ob01 = __float_as_uint(zpB[96]);
                    unsigned int ob10 = __float_as_uint(zpB[8]);
                    unsigned int ob11 = __float_as_uint(zpB[104]);
                    mma_bf16(a0e, afr[kk], eb00, eb01);
                    mma_bf16(a1e, afr[kk], eb10, eb11);
                    mma_bf16(a0o, afr[kk + 1], ob00, ob01);
                    mma_bf16(a1o, afr[kk + 1], ob10, ob11);
                }
                float acc0[4], acc1[4];
#pragma unroll
                for (int i = 0; i < 4; ++i) {
                    acc0[i] = a0e[i] + a0o[i];
                    acc1[i] = a1e[i] + a1o[i];
                }
                *(float2*)(sm_g + j0 * 20 + cp)           = make_float2(acc0[0], acc0[1]);
                *(float2*)(sm_g + (j0 + 8) * 20 + cp)     = make_float2(acc0[2], acc0[3]);
                *(float2*)(sm_g + j0 * 20 + cp + 8)       = make_float2(acc1[0], acc1[1]);
                *(float2*)(sm_g + (j0 + 8) * 20 + cp + 8) = make_float2(acc1[2], acc1[3]);
            }
            BAR_ARRIVE(4 + (t & 1), TPB);      // x buffer (t&1) free for t+2
            BAR_SYNC(6, 416);                  // sm_g visible within H-group

            // ---- C: cell update (400 threads x 2 batches) ----
            if (tid < 400) {
                float2 gi2 = *(const float2*)(sm_g + u_c * 20 + 2 * bq8);
                float2 gf2 = *(const float2*)(sm_g + (u_c + 50) * 20 + 2 * bq8);
                float2 gg2 = *(const float2*)(sm_g + (u_c + 100) * 20 + 2 * bq8);
                float2 go2 = *(const float2*)(sm_g + (u_c + 150) * 20 + 2 * bq8);
                float bi = sm_b[u_c], bf = sm_b[u_c + 50];
                float bg = sm_b[u_c + 100], bo = sm_b[u_c + 150];
                float gi[2] = {gi2.x + bi, gi2.y + bi};
                float gf[2] = {gf2.x + bf, gf2.y + bf};
                float gg[2] = {gg2.x + bg, gg2.y + bg};
                float go[2] = {go2.x + bo, go2.y + bo};
                float h2[2];
#pragma unroll
                for (int i = 0; i < 2; ++i) {
                    float c = sigf(gf[i]) * creg[i] + sigf(gi[i]) * tanhfast(gg[i]);
                    float h = sigf(go[i]) * tanhfast(c);
                    creg[i] = c;
                    h2[i] = h;
                }
                // publish ring first (shortens inter-layer hop), then local stage
                float* dst = (layer < NL - 1)
                    ? (d_ring + (((size_t)layer * RINGN + (t & (RINGN - 1))) * NSL + s) * HH * BS
                       + u_c * BS + 2 * bq8)
                    : (d_hT + ((size_t)t * NSL + s) * HH * BS + u_c * BS + 2 * bq8);
                __stcg((float2*)dst, make_float2(h2[0], h2[1]));
#pragma unroll
                for (int i = 0; i < 2; ++i)
                    stage_zh(zh, 2 * bq8 + i, u_c, h2[i]);
                if (t == TT - 1 && has_state) {
                    size_t base2 = (size_t)BATCH * DOUT * TT;
#pragma unroll
                    for (int i = 0; i < 2; ++i) {
                        size_t sidx = ((size_t)layer * BATCH + b0 + 2 * bq8 + i) * HH + u_c;
                        out[base2 + sidx] = h2[i];
                        out[base2 + (size_t)NL * BATCH * HH + sidx] = creg[i];
                    }
                }
            }
            BAR_SYNC(6, 416);                  // h(t) staged + ring stores drained
            if (tid == 0) st_release_gpu(prog_me, t + 1);
        }
    } else {
        // ======================= X-group (staging) =======================
        for (int t = 0; t < TT; ++t) {
            // poll prev first (overlaps the buffer-free wait)
            if (layer > 0) {
                if (lane == 0) { while (ld_acquire_gpu(prog_prev) < t + 1) __nanosleep(32); }
                __syncwarp();
            }
            if (t >= 2) BAR_SYNC(4 + (t & 1), TPB);   // x buffer (t&1) free
            __nv_bfloat16* zx = reinterpret_cast<__nv_bfloat16*>(sm + OFF_ZX + (t & 1) * 2304);
            if (layer == 0) {
                const float* xp = d_xT + ((size_t)t * NSL + s) * DIN * BS;
                for (int idx = tid - 416; idx < DIN * BS; idx += 64) {
                    int d = idx >> 4, n = idx & 15;
                    stage_zx(zx, n, d, xp[d * BS + n]);
                }
            } else {
                const float* rp = d_ring +
                    (((size_t)(layer - 1) * RINGN + (t & (RINGN - 1))) * NSL + s) * HH * BS;
                for (int idx = tid - 416; idx < HH * BS; idx += 64) {
                    int d = idx >> 4, n = idx & 15;
                    stage_zx(zx, n, d, __ldcg(rp + d * BS + n));
                }
            }
            BAR_SYNC(7, 64);                   // staging complete across X warps
            if (tid == 416 && layer > 0 && (((t & 3) == 3) || t == TT - 1))
                st_release_gpu(cons_me, t + 1);
            BAR_ARRIVE(2 + (t & 1), TPB);      // x(t) ready
        }
    }
}

extern "C" void kernel_launch(void* const* d_in, const int* in_sizes, int n_in,
                              void* d_out, int out_size) {
    const float* x    = (const float*)d_in[0];
    const float* hn   = (const float*)d_in[1];
    const float* cn   = (const float*)d_in[2];
    const float* Wih0 = (const float*)d_in[3];
    const float* Wih  = (const float*)d_in[4];
    const float* Whh  = (const float*)d_in[5];
    const float* bih  = (const float*)d_in[6];
    const float* bhh  = (const float*)d_in[7];
    const float* fcw  = (const float*)d_in[8];
    const float* fcb  = (const float*)d_in[9];
    float* out = (float*)d_out;

    const long long full = (long long)BATCH * DOUT * TT + 2LL * NL * BATCH * HH;
    int has_state = (out_size >= full) ? 1 : 0;

    cudaFuncSetAttribute(lstm_kernel, cudaFuncAttributeMaxDynamicSharedMemorySize,
                         SMEM_FLOATS * sizeof(float));

    xpose_kernel<<<(BATCH * DIN * TT + 255) / 256, 256>>>(x);
    lstm_kernel<<<NL * NSL + NSL, TPB, SMEM_FLOATS * sizeof(float)>>>(
        hn, cn, Wih0, Wih, Whh, bih, bhh, fcw, fcb, out, has_state);
}

// round 17
// speedup vs baseline: 1.0428x; 1.0428x over previous
#include <cuda_runtime.h>

#define NL    64
#define HH    50
#define G4    200
#define DIN   60
#define BATCH 32
#define TT    2048
#define DOUT  50
#define BS    16
#define NSL   2
#define RINGN 16
#define TPB   256   // warps 0-3: H-group (tid 0..127), warps 4-7: X-group (tid 128..255)

// ---- scratch (device globals) ----
__device__ float d_ring[(NL - 1) * RINGN * NSL * HH * BS];  // [l][slot][s][u][16]
__device__ int   d_prog[NSL * NL];
__device__ int   d_cons[NSL * NL];
__device__ float d_xT[TT * NSL * DIN * BS];                 // [t][s][d][16]
__device__ float d_hT[TT * NSL * HH * BS];                  // [t][s][u][16]

// lstm smem (floats)
#define OFF_B   0      // [200] pad 208
#define OFF_XS  208    // 2 x [60][16] double buffer
#define OFF_HS  2128   // [50][16]
#define OFF_GH  2928   // 3200
#define OFF_GX  6128   // 2 x 3200 double buffer
#define SMEM_FLOATS 12528
// fc smem
#define FOFF_W  0
#define FOFF_B  2512
#define FOFF_H  2576   // [50][16]

__device__ __forceinline__ float sigf(float x) {
    return __fdividef(1.0f, 1.0f + __expf(-x));
}
__device__ __forceinline__ float tanhfast(float x) {
    return 1.0f - __fdividef(2.0f, __expf(2.0f * x) + 1.0f);
}
__device__ __forceinline__ unsigned long long pack2(float x) {
    unsigned long long r;
    asm("mov.b64 %0, {%1, %1};" : "=l"(r) : "f"(x));
    return r;
}
__device__ __forceinline__ void fma2(unsigned long long& d, unsigned long long a,
                                     unsigned long long b) {
    asm("fma.rn.f32x2 %0, %1, %2, %0;" : "+l"(d) : "l"(a), "l"(b));
}
__device__ __forceinline__ int ld_acquire_gpu(const int* p) {
    int v;
    asm volatile("ld.acquire.gpu.global.b32 %0, [%1];" : "=r"(v) : "l"(p) : "memory");
    return v;
}
__device__ __forceinline__ void st_release_gpu(int* p, int v) {
    asm volatile("st.release.gpu.global.b32 [%0], %1;" :: "l"(p), "r"(v) : "memory");
}

#define BAR_SYNC(id, n) asm volatile("bar.sync %0, %1;" :: "r"(id), "r"(n) : "memory")

__global__ void xpose_kernel(const float* __restrict__ x) {
    if (blockIdx.x == 0 && threadIdx.x < NSL * NL) {
        d_prog[threadIdx.x] = 0;
        d_cons[threadIdx.x] = 0;
    }
    int idx = blockIdx.x * blockDim.x + threadIdx.x;  // (b*DIN+d)*T + t
    if (idx >= BATCH * DIN * TT) return;
    int t = idx % TT;
    int bd = idx / TT;
    int d = bd % DIN, b = bd / DIN;
    d_xT[(((size_t)t * NSL + b / BS) * DIN + d) * BS + (b % BS)] = x[idx];
}

// B2: gx = x @ Wih^T for one j-pair (two gate rows in regs), 16 batches
__device__ __forceinline__ void do_b2(const float* xbuf, float* gxout,
                                      const float* wA, const float* wB, int j0) {
    unsigned long long accA[8], accB[8];
#pragma unroll
    for (int p = 0; p < 8; ++p) { accA[p] = 0ull; accB[p] = 0ull; }
#pragma unroll
    for (int k = 0; k < 60; ++k) {
        unsigned long long w0 = pack2(wA[k]);
        unsigned long long w1 = pack2(wB[k]);
        const ulonglong2* xp2 = (const ulonglong2*)(xbuf + k * BS);
        ulonglong2 q0 = xp2[0], q1 = xp2[1], q2 = xp2[2], q3 = xp2[3];
        fma2(accA[0], q0.x, w0); fma2(accA[1], q0.y, w0);
        fma2(accA[2], q1.x, w0); fma2(accA[3], q1.y, w0);
        fma2(accA[4], q2.x, w0); fma2(accA[5], q2.y, w0);
        fma2(accA[6], q3.x, w0); fma2(accA[7], q3.y, w0);
        fma2(accB[0], q0.x, w1); fma2(accB[1], q0.y, w1);
        fma2(accB[2], q1.x, w1); fma2(accB[3], q1.y, w1);
        fma2(accB[4], q2.x, w1); fma2(accB[5], q2.y, w1);
        fma2(accB[6], q3.x, w1); fma2(accB[7], q3.y, w1);
    }
#pragma unroll
    for (int p = 0; p < 8; ++p) {
        ulonglong2 v; v.x = accA[p]; v.y = accB[p];
        *(ulonglong2*)(gxout + (p * G4 + j0) * 2) = v;
    }
}

__global__ void __launch_bounds__(TPB, 1) lstm_kernel(
    const float* __restrict__ hn,  const float* __restrict__ cn,
    const float* __restrict__ Wih0, const float* __restrict__ Wih,
    const float* __restrict__ Whh, const float* __restrict__ bih,
    const float* __restrict__ bhh, const float* __restrict__ fcw,
    const float* __restrict__ fcb, float* __restrict__ out, int has_state)
{
    extern __shared__ float sm[];
    const int tid  = threadIdx.x;
    const int lane = tid & 31;

    // ================= FC consumer role (blocks 128,129) =================
    if (blockIdx.x >= NL * NSL) {
        const int s = blockIdx.x - NL * NSL;
        float* sm_w  = sm + FOFF_W;
        float* sm_fb = sm + FOFF_B;
        float* sm_h  = sm + FOFF_H;
        for (int i = tid; i < DOUT * HH; i += TPB) sm_w[i] = fcw[i];
        for (int i = tid; i < DOUT; i += TPB)      sm_fb[i] = fcb[i];
        __syncthreads();
        const int* prog63 = &d_prog[s * NL + NL - 1];
        for (int t = 0; t < TT; ++t) {
            if (lane == 0) { while (ld_acquire_gpu(prog63) < t + 1) __nanosleep(128); }
            __syncwarp();
            const float* hp = d_hT + ((size_t)t * NSL + s) * HH * BS;
            for (int idx = tid; idx < HH * 4; idx += TPB) {
                float4 v = __ldcg((const float4*)(hp + idx * 4));
                *(float4*)(sm_h + idx * 4) = v;
            }
            __syncthreads();
            if (tid < G4) {
                const int o  = tid % DOUT;
                const int bq = tid / DOUT;
#pragma unroll
                for (int i = 0; i < 4; ++i) {
                    int b = bq * 4 + i;
                    float acc = sm_fb[o];
#pragma unroll 5
                    for (int u = 0; u < HH; ++u)
                        acc = fmaf(sm_h[u * BS + b], sm_w[o * HH + u], acc);
                    out[((size_t)(s * BS + b) * DOUT + o) * TT + t] = sigf(acc);
                }
            }
            __syncthreads();
        }
        return;
    }

    // ========================= LSTM layer role =========================
    const int  layer = blockIdx.x >> 1;
    const int  s     = blockIdx.x & 1;
    const int  b0    = s * BS;
    const int  K1    = (layer == 0) ? DIN : HH;
    const bool isX   = (tid >= 128);
    const int  lt    = isX ? (tid - 128) : tid;   // local id within group
    const bool act   = (lt < 100);                // j-pair / C active
    const int  j0    = lt * 2;

    float* sm_b  = sm + OFF_B;
    float* sm_hs = sm + OFF_HS;
    float* sm_gh = sm + OFF_GH;

    // ---- init: zero xs (both buffers), bias, h0 ----
    for (int i = tid; i < 2 * DIN * BS; i += TPB) sm[OFF_XS + i] = 0.0f;
    for (int jj = tid; jj < G4; jj += TPB)
        sm_b[jj] = bih[layer * G4 + jj] + bhh[layer * G4 + jj];
    for (int idx = tid; idx < HH * BS; idx += TPB) {
        int u = idx / BS, b = idx % BS;
        sm_hs[u * BS + b] = hn[((size_t)layer * BATCH + b0 + b) * HH + u];
    }

    // ---- weights into regs: two gate-row columns per thread ----
    float wA[60], wB[60];
    if (act) {
        if (isX) {
            const float* wg = (layer == 0) ? Wih0 : (Wih + (size_t)(layer - 1) * G4 * HH);
#pragma unroll
            for (int k = 0; k < 60; ++k) {
                wA[k] = (k < K1) ? wg[j0 * K1 + k] : 0.0f;
                wB[k] = (k < K1) ? wg[(j0 + 1) * K1 + k] : 0.0f;
            }
        } else {
            const float* wh = Whh + (size_t)layer * G4 * HH;
#pragma unroll
            for (int k = 0; k < 50; ++k) {
                wA[k] = wh[j0 * HH + k];
                wB[k] = wh[(j0 + 1) * HH + k];
            }
        }
    }

    // ---- cell state in regs: C split across groups ----
    // H (act): batches 0..7; X (act): batches 8..15. 4 batches per thread.
    float creg[4];
    const int u_c  = lt % HH;
    const int q_c  = act ? (lt / HH) : 0;            // 0 or 1
    const int cb0  = (isX ? 8 : 0) + q_c * 4;        // first batch owned
    if (act) {
#pragma unroll
        for (int i = 0; i < 4; ++i)
            creg[i] = cn[((size_t)layer * BATCH + b0 + cb0 + i) * HH + u_c];
    }
    __syncthreads();

    int* prog_prev = (layer > 0)      ? &d_prog[s * NL + layer - 1] : 0;
    int* cons_next = (layer < NL - 1) ? &d_cons[s * NL + layer + 1] : 0;
    int* prog_me   = &d_prog[s * NL + layer];
    int* cons_me   = &d_cons[s * NL + layer];

    int cons_cache = 0;  // lane0-only cached view of cons_next

    // ================= X prologue: stage x(0) + gx(0) =================
    if (isX) {
        if (layer > 0) {
            if (lane == 0) { while (ld_acquire_gpu(prog_prev) < 1) __nanosleep(32); }
            __syncwarp();
        }
        float* xbuf = sm + OFF_XS;   // parity 0
        if (layer == 0) {
            const float* xp = d_xT + (size_t)s * DIN * BS;
            for (int idx = lt; idx < DIN * 4; idx += 128)
                *(float4*)(xbuf + idx * 4) = *(const float4*)(xp + idx * 4);
        } else {
            const float* rp = d_ring + ((size_t)(layer - 1) * RINGN * NSL + s) * HH * BS;
            for (int idx = lt; idx < HH * 4; idx += 128)
                *(float4*)(xbuf + idx * 4) = __ldcg((const float4*)(rp + idx * 4));
        }
        BAR_SYNC(7, 128);
        if (act) do_b2(xbuf, sm + OFF_GX, wA, wB, j0);
    }

    // ========================= main loop =========================
    for (int t = 0; t < TT; ++t) {
        if (!isX) {
            // ---- H: cached backpressure (hoisted) + B1 ----
            if (layer < NL - 1 && t >= RINGN && lane == 0) {
                int need = t - RINGN + 1;
                if (cons_cache < need) {
                    cons_cache = ld_acquire_gpu(cons_next);
                    while (cons_cache < need) {
                        __nanosleep(32);
                        cons_cache = ld_acquire_gpu(cons_next);
                    }
                }
            }
            if (act) {
                unsigned long long accA[8], accB[8];
                unsigned long long bA = pack2(sm_b[j0]);
                unsigned long long bB = pack2(sm_b[j0 + 1]);
#pragma unroll
                for (int p = 0; p < 8; ++p) { accA[p] = bA; accB[p] = bB; }
#pragma unroll
                for (int k = 0; k < 50; ++k) {
                    unsigned long long w0 = pack2(wA[k]);
                    unsigned long long w1 = pack2(wB[k]);
                    const ulonglong2* hp = (const ulonglong2*)(sm_hs + k * BS);
                    ulonglong2 q0 = hp[0], q1 = hp[1], q2 = hp[2], q3 = hp[3];
                    fma2(accA[0], q0.x, w0); fma2(accA[1], q0.y, w0);
                    fma2(accA[2], q1.x, w0); fma2(accA[3], q1.y, w0);
                    fma2(accA[4], q2.x, w0); fma2(accA[5], q2.y, w0);
                    fma2(accA[6], q3.x, w0); fma2(accA[7], q3.y, w0);
                    fma2(accB[0], q0.x, w1); fma2(accB[1], q0.y, w1);
                    fma2(accB[2], q1.x, w1); fma2(accB[3], q1.y, w1);
                    fma2(accB[4], q2.x, w1); fma2(accB[5], q2.y, w1);
                    fma2(accB[6], q3.x, w1); fma2(accB[7], q3.y, w1);
                }
#pragma unroll
                for (int p = 0; p < 8; ++p) {
                    ulonglong2 v; v.x = accA[p]; v.y = accB[p];
                    *(ulonglong2*)(sm_gh + (p * G4 + j0) * 2) = v;
                }
            }
        } else {
            // ---- X: stage x(t+1) + gx(t+1) (one step ahead) ----
            int u = t + 1;
            if (u < TT) {
                if (layer > 0) {
                    if (lane == 0) { while (ld_acquire_gpu(prog_prev) < u + 1) __nanosleep(32); }
                    __syncwarp();
                }
                float* xbuf = sm + OFF_XS + (u & 1) * (DIN * BS);
                if (layer == 0) {
                    const float* xp = d_xT + ((size_t)u * NSL + s) * DIN * BS;
                    for (int idx = lt; idx < DIN * 4; idx += 128)
                        *(float4*)(xbuf + idx * 4) = *(const float4*)(xp + idx * 4);
                } else {
                    const float* rp = d_ring +
                        (((size_t)(layer - 1) * RINGN + (u & (RINGN - 1))) * NSL + s) * HH * BS;
                    for (int idx = lt; idx < HH * 4; idx += 128)
                        *(float4*)(xbuf + idx * 4) = __ldcg((const float4*)(rp + idx * 4));
                }
            }
            BAR_SYNC(7, 128);
            if (tid == 128 && layer > 0 && u < TT && (((u & 3) == 3) || u == TT - 1))
                st_release_gpu(cons_me, u + 1);
            if (u < TT && act)
                do_b2(sm + OFF_XS + (u & 1) * (DIN * BS),
                      sm + OFF_GX + (u & 1) * 3200, wA, wB, j0);
            // cached backpressure for this group's ring stores in C(t)
            if (layer < NL - 1 && t >= RINGN && lane == 0) {
                int need = t - RINGN + 1;
                if (cons_cache < need) {
                    cons_cache = ld_acquire_gpu(cons_next);
                    while (cons_cache < need) {
                        __nanosleep(32);
                        cons_cache = ld_acquire_gpu(cons_next);
                    }
                }
            }
        }

        __syncthreads();   // sync1: gh(t) + gx(t) ready; h(t-1) reads done

        // ---- C: cell update, 200 threads x 4 batches (both groups) ----
        if (act) {
            const float* gx = sm + OFF_GX + (t & 1) * 3200;
            float h4[4];
#pragma unroll
            for (int i = 0; i < 4; ++i) {
                int b    = cb0 + i;
                int base = (b >> 1) * G4 * 2 + (b & 1);
                float gi = gx[base + u_c * 2]         + sm_gh[base + u_c * 2];
                float gf = gx[base + (50 + u_c) * 2]  + sm_gh[base + (50 + u_c) * 2];
                float gg = gx[base + (100 + u_c) * 2] + sm_gh[base + (100 + u_c) * 2];
                float go = gx[base + (150 + u_c) * 2] + sm_gh[base + (150 + u_c) * 2];
                float c = sigf(gf) * creg[i] + sigf(gi) * tanhfast(gg);
                float h = sigf(go) * tanhfast(c);
                creg[i] = c;
                h4[i] = h;
            }
            float4 hv = make_float4(h4[0], h4[1], h4[2], h4[3]);
            float* dst = (layer < NL - 1)
                ? (d_ring + (((size_t)layer * RINGN + (t & (RINGN - 1))) * NSL + s) * HH * BS
                   + u_c * BS + cb0)
                : (d_hT + ((size_t)t * NSL + s) * HH * BS + u_c * BS + cb0);
            __stcg((float4*)dst, hv);
            *(float4*)(sm_hs + u_c * BS + cb0) = hv;
            if (t == TT - 1 && has_state) {
                size_t base2 = (size_t)BATCH * DOUT * TT;
#pragma unroll
                for (int i = 0; i < 4; ++i) {
                    size_t sidx = ((size_t)layer * BATCH + b0 + cb0 + i) * HH + u_c;
                    out[base2 + sidx] = h4[i];
                    out[base2 + (size_t)NL * BATCH * HH + sidx] = creg[i];
                }
            }
        }

        __syncthreads();   // sync2: h(t) staged; ring stores drained; gx[t&1] free

        if (tid == 0) st_release_gpu(prog_me, t + 1);
    }
}

extern "C" void kernel_launch(void* const* d_in, const int* in_sizes, int n_in,
                              void* d_out, int out_size) {
    const float* x    = (const float*)d_in[0];
    const float* hn   = (const float*)d_in[1];
    const float* cn   = (const float*)d_in[2];
    const float* Wih0 = (const float*)d_in[3];
    const float* Wih  = (const float*)d_in[4];
    const float* Whh  = (const float*)d_in[5];
    const float* bih  = (const float*)d_in[6];
    const float* bhh  = (const float*)d_in[7];
    const float* fcw  = (const float*)d_in[8];
    const float* fcb  = (const float*)d_in[9];
    float* out = (float*)d_out;

    const long long full = (long long)BATCH * DOUT * TT + 2LL * NL * BATCH * HH;
    int has_state = (out_size >= full) ? 1 : 0;

    cudaFuncSetAttribute(lstm_kernel, cudaFuncAttributeMaxDynamicSharedMemorySize,
                         SMEM_FLOATS * sizeof(float));

    xpose_kernel<<<(BATCH * DIN * TT + 255) / 256, 256>>>(x);
    lstm_kernel<<<NL * NSL + NSL, TPB, SMEM_FLOATS * sizeof(float)>>>(
        hn, cn, Wih0, Wih, Whh, bih, bhh, fcw, fcb, out, has_state);
}